// round 9
// baseline (speedup 1.0000x reference)
#include <cuda_runtime.h>
#include <math.h>

#define BS 2
#define CH 100
#define T 100
#define KNN 3
#define RES_INNER 12
#define RES_CTX 16
#define RES_TOT 28
#define DT 5000
#define OUT_C_STRIDE 140000
#define NT_TILES 5            // tiles of 1024 dt (last = 904)

#define CSPLIT_IN 10
#define CPB_IN 10
#define CSPLIT_CTX 5
#define CPB_CTX 20

#define KNN_GRID   (BS * T)                                   // 200
#define INNER_GRID (BS * RES_INNER * NT_TILES * CSPLIT_IN)    // 1200
#define CTX_GRID   (BS * RES_CTX * NT_TILES * CSPLIT_CTX)     // 800
#define TOTAL_GRID (KNN_GRID + INNER_GRID + CTX_GRID)         // 2200

__device__ float g_ctx[BS * T * KNN];
__device__ unsigned g_done = 0;
__device__ unsigned g_exit = 0;

// ---------------- kNN body: one block per (b,t); 256 thr ----------------
__device__ void knn_body(const float* __restrict__ x, int bt) {
    __shared__ float sh_dot[2][T], sh_x3[2][T], sh_cs[2][T];
    __shared__ float sh_pd[T], sh_colsum[T], sh_xxt;

    const int b = bt / T, t = bt % T;
    const int tid = threadIdx.x;
    const int q = tid >> 7;
    const int s = tid & 127;

    const float* xb = x + (size_t)b * CH * T;

    if (s < T) {
        const int c0 = q * 50;
        float dot = 0.f, x3 = 0.f, cs = 0.f;
        #pragma unroll 5
        for (int c = c0; c < c0 + 50; ++c) {
            float xs = xb[c * T + s];
            float xt = xb[c * T + t];
            dot = fmaf(xt, xs, dot);
            x3  = fmaf(xs * xs, xs, x3);
            cs += xs;
        }
        sh_dot[q][s] = dot; sh_x3[q][s] = x3; sh_cs[q][s] = cs;
    }
    __syncthreads();

    if (tid < T) {
        float dot = sh_dot[0][tid] + sh_dot[1][tid];
        float x3  = sh_x3[0][tid]  + sh_x3[1][tid];
        sh_colsum[tid] = sh_cs[0][tid] + sh_cs[1][tid];
        if (tid == t) sh_xxt = x3;
        sh_pd[tid] = 2.0f * dot - x3;
    }
    __syncthreads();
    if (tid < T) sh_pd[tid] -= sh_xxt;
    __syncthreads();

    if (tid < 32) {
        #pragma unroll
        for (int k = 0; k < KNN; ++k) {
            float bv = -INFINITY; int bi = T;
            #pragma unroll
            for (int i = tid; i < T; i += 32) {
                float v = sh_pd[i];
                if (v > bv) { bv = v; bi = i; }
            }
            #pragma unroll
            for (int off = 16; off > 0; off >>= 1) {
                float ov = __shfl_down_sync(0xffffffffu, bv, off);
                int   oi = __shfl_down_sync(0xffffffffu, bi, off);
                if (ov > bv || (ov == bv && oi < bi)) { bv = ov; bi = oi; }
            }
            bi = __shfl_sync(0xffffffffu, bi, 0);
            if (tid == 0) {
                g_ctx[(b * T + t) * KNN + k] = sh_colsum[bi] / (float)CH;
                sh_pd[bi] = -INFINITY;
            }
            __syncwarp();
        }
        if (tid == 0) {
            __threadfence();
            atomicAdd(&g_done, 1u);
        }
    }
}

// ---------------- inner align (r<12): consec-4 dt, 5-load fast path, STG.128 ----------------
__device__ void inner_body(const float* __restrict__ x, float* __restrict__ out, int blk) {
    int cblk = blk % CSPLIT_IN;  blk /= CSPLIT_IN;
    int tile = blk % NT_TILES;   blk /= NT_TILES;
    int r    = blk % RES_INNER;
    int b    = blk / RES_INNER;
    const int tid = threadIdx.x;

    const int tsz = (tile < 4) ? 1024 : (DT - 4096);   // 904 on last tile
    const int idx = tid * 4;
    if (idx >= tsz) return;                            // no barriers below

    const int dt0 = tile * 1024 + idx;                 // 4 consecutive dt, same d row
    const int d   = dt0 / T;
    const int t0  = dt0 - d * T;

    int   lo[4], hi[4];
    float wlo[4], whi[4];

    #pragma unroll
    for (int j = 0; j < 4; ++j) {
        int t = t0 + j;
        bool va     = (t + d) < T;
        float cl    = (float)(d + 1);
        float start = va ? ((float)t - cl * 0.5f) : 0.0f;
        float end   = va ? ((float)(t + d) + cl * 0.5f) : 0.0f;
        float binw  = __fdiv_rn(end - start, (float)RES_INNER);
        float coord = __fadd_rn(start, __fmul_rn((float)r + 0.5f, binw));
        bool valid  = (coord >= -1.0f) && (coord <= (float)T);
        float lof   = floorf(coord);
        float frac  = coord - lof;
        int loi = (int)lof;
        loi = loi < 0 ? 0 : (loi > T - 1 ? T - 1 : loi);
        int hii = loi + 1 > T - 1 ? T - 1 : loi + 1;
        lo[j] = loi; hi[j] = hii;
        wlo[j] = valid ? (1.0f - frac) : 0.0f;
        whi[j] = valid ? frac : 0.0f;
    }

    // fast path: lo chain is consecutive and unclamped -> 5 shared loads
    const bool fast = (lo[1] == lo[0] + 1) && (lo[2] == lo[0] + 2) &&
                      (lo[3] == lo[0] + 3) && (lo[0] + 4 <= T - 1);

    const int c0 = cblk * CPB_IN;
    const float* src = x + ((size_t)b * CH + c0) * T;
    float* gdst = out + ((b * CH + c0) * RES_TOT + r) * DT + dt0;

    if (fast) {
        const int p = lo[0];
        #pragma unroll
        for (int c = 0; c < CPB_IN; ++c) {
            float v0 = __ldg(src + p);
            float v1 = __ldg(src + p + 1);
            float v2 = __ldg(src + p + 2);
            float v3 = __ldg(src + p + 3);
            float v4 = __ldg(src + p + 4);
            float4 o;
            o.x = fmaf(whi[0], v1, wlo[0] * v0);
            o.y = fmaf(whi[1], v2, wlo[1] * v1);
            o.z = fmaf(whi[2], v3, wlo[2] * v2);
            o.w = fmaf(whi[3], v4, wlo[3] * v3);
            *reinterpret_cast<float4*>(gdst) = o;
            src  += T;
            gdst += OUT_C_STRIDE;
        }
    } else {
        #pragma unroll
        for (int c = 0; c < CPB_IN; ++c) {
            float4 o;
            o.x = fmaf(whi[0], __ldg(src + hi[0]), wlo[0] * __ldg(src + lo[0]));
            o.y = fmaf(whi[1], __ldg(src + hi[1]), wlo[1] * __ldg(src + lo[1]));
            o.z = fmaf(whi[2], __ldg(src + hi[2]), wlo[2] * __ldg(src + lo[2]));
            o.w = fmaf(whi[3], __ldg(src + hi[3]), wlo[3] * __ldg(src + lo[3]));
            *reinterpret_cast<float4*>(gdst) = o;
            src  += T;
            gdst += OUT_C_STRIDE;
        }
    }
}

// ---------------- ctx align (r>=12): 3-coeff precompute, direct STG.128 ----------------
__device__ void ctx_body(float* __restrict__ out, int blk) {
    int cblk = blk % CSPLIT_CTX;  blk /= CSPLIT_CTX;
    int tile = blk % NT_TILES;    blk /= NT_TILES;
    int rr   = blk % RES_CTX;
    int b    = blk / RES_CTX;
    const int tid = threadIdx.x;

    // wait for kNN blocks (IDs 0..199 guaranteed wave-1 resident)
    if (tid == 0) {
        while (atomicAdd(&g_done, 0u) < (unsigned)KNN_GRID) { __nanosleep(64); }
        __threadfence();
    }
    __syncthreads();

    const int tsz = (tile < 4) ? 1024 : (DT - 4096);
    const int idx = tid * 4;

    if (idx < tsz) {
        const int dt0 = tile * 1024 + idx;
        const int d   = dt0 / T;
        const int t0  = dt0 - d * T;

        float a0[4], a1[4], a2[4];
        #pragma unroll
        for (int j = 0; j < 4; ++j) {
            int t = t0 + j;
            bool va     = (t + d) < T;
            float cl    = (float)(d + 1);
            float start = va ? ((float)t - cl * 0.5f) : 0.0f;
            float end   = va ? ((float)(t + d) + cl * 0.5f) : 0.0f;
            float binw  = (end - start) * 0.0625f;       // /16 exact
            float coord = __fadd_rn(start, __fmul_rn((float)rr + 0.5f, binw));
            bool valid  = (coord >= -1.0f) && (coord <= (float)KNN);
            float lof   = floorf(coord);
            float frac  = coord - lof;
            int loi = (int)lof;
            loi = loi < 0 ? 0 : (loi > KNN - 1 ? KNN - 1 : loi);
            int hii = loi + 1 > KNN - 1 ? KNN - 1 : loi + 1;
            float wlo = valid ? (1.0f - frac) : 0.0f;
            float whi = valid ? frac : 0.0f;
            float c0a = 0.f, c1a = 0.f, c2a = 0.f;
            if (loi == 0) c0a += wlo; else if (loi == 1) c1a += wlo; else c2a += wlo;
            if (hii == 0) c0a += whi; else if (hii == 1) c1a += whi; else c2a += whi;
            a0[j] = c0a; a1[j] = c1a; a2[j] = c2a;
        }

        const int c0 = cblk * CPB_CTX;
        const float* cr = g_ctx + (b * CH + c0) * KNN;
        float* gdst = out + ((b * CH + c0) * RES_TOT + (RES_INNER + rr)) * DT + dt0;

        #pragma unroll 4
        for (int c = 0; c < CPB_CTX; ++c) {
            float g0 = __ldg(cr + 0), g1 = __ldg(cr + 1), g2 = __ldg(cr + 2);
            float4 o;
            o.x = fmaf(a2[0], g2, fmaf(a1[0], g1, a0[0] * g0));
            o.y = fmaf(a2[1], g2, fmaf(a1[1], g1, a0[1] * g0));
            o.z = fmaf(a2[2], g2, fmaf(a1[2], g1, a0[2] * g0));
            o.w = fmaf(a2[3], g2, fmaf(a1[3], g1, a0[3] * g0));
            *reinterpret_cast<float4*>(gdst) = o;
            cr   += KNN;
            gdst += OUT_C_STRIDE;
        }
    }

    // last ctx block resets counters for deterministic graph replay
    __syncthreads();
    if (tid == 0) {
        unsigned v = atomicAdd(&g_exit, 1u);
        if (v == (unsigned)(CTX_GRID - 1)) {
            g_done = 0;
            g_exit = 0;
            __threadfence();
        }
    }
}

// ---------------- fused kernel ----------------
__global__ void __launch_bounds__(256)
graph_align_fused(const float* __restrict__ x, float* __restrict__ out) {
    unsigned bid = blockIdx.x;
    if (bid < KNN_GRID) {
        knn_body(x, (int)bid);
    } else if (bid < KNN_GRID + INNER_GRID) {
        inner_body(x, out, (int)(bid - KNN_GRID));
    } else {
        ctx_body(out, (int)(bid - KNN_GRID - INNER_GRID));
    }
}

extern "C" void kernel_launch(void* const* d_in, const int* in_sizes, int n_in,
                              void* d_out, int out_size) {
    const float* x = (const float*)d_in[0];
    float* out = (float*)d_out;
    graph_align_fused<<<TOTAL_GRID, 256>>>(x, out);
}

// round 10
// speedup vs baseline: 1.0815x; 1.0815x over previous
#include <cuda_runtime.h>
#include <math.h>

#define BS 2
#define CH 100
#define T 100
#define KNN 3
#define RES_INNER 12
#define RES_CTX 16
#define RES_TOT 28
#define DT 5000
#define OUT_C_STRIDE 140000
#define NT_TILES 5            // tiles of 1024 dt (last = 904)

#define CSPLIT_IN 10
#define CPB_IN 10
#define CSPLIT_CTX 5
#define CPB_CTX 20

#define KNN_GRID   (BS * T)                                   // 200
#define INNER_GRID (BS * RES_INNER * NT_TILES * CSPLIT_IN)    // 1200
#define CTX_GRID   (BS * RES_CTX * NT_TILES * CSPLIT_CTX)     // 800
#define TOTAL_GRID (KNN_GRID + INNER_GRID + CTX_GRID)         // 2200

__device__ float g_ctx[BS * T * KNN];
__device__ unsigned g_done = 0;
__device__ unsigned g_exit = 0;

// ---------------- kNN body: one block per (b,t); 256 thr ----------------
__device__ void knn_body(const float* __restrict__ x, int bt) {
    __shared__ float sh_dot[2][T], sh_x3[2][T], sh_cs[2][T];
    __shared__ float sh_pd[T], sh_colsum[T], sh_xxt;

    const int b = bt / T, t = bt % T;
    const int tid = threadIdx.x;
    const int q = tid >> 7;
    const int s = tid & 127;

    const float* xb = x + (size_t)b * CH * T;

    if (s < T) {
        const int c0 = q * 50;
        float dot = 0.f, x3 = 0.f, cs = 0.f;
        #pragma unroll 5
        for (int c = c0; c < c0 + 50; ++c) {
            float xs = xb[c * T + s];
            float xt = xb[c * T + t];
            dot = fmaf(xt, xs, dot);
            x3  = fmaf(xs * xs, xs, x3);
            cs += xs;
        }
        sh_dot[q][s] = dot; sh_x3[q][s] = x3; sh_cs[q][s] = cs;
    }
    __syncthreads();

    if (tid < T) {
        float dot = sh_dot[0][tid] + sh_dot[1][tid];
        float x3  = sh_x3[0][tid]  + sh_x3[1][tid];
        sh_colsum[tid] = sh_cs[0][tid] + sh_cs[1][tid];
        if (tid == t) sh_xxt = x3;
        sh_pd[tid] = 2.0f * dot - x3;
    }
    __syncthreads();
    if (tid < T) sh_pd[tid] -= sh_xxt;
    __syncthreads();

    if (tid < 32) {
        #pragma unroll
        for (int k = 0; k < KNN; ++k) {
            float bv = -INFINITY; int bi = T;
            #pragma unroll
            for (int i = tid; i < T; i += 32) {
                float v = sh_pd[i];
                if (v > bv) { bv = v; bi = i; }
            }
            #pragma unroll
            for (int off = 16; off > 0; off >>= 1) {
                float ov = __shfl_down_sync(0xffffffffu, bv, off);
                int   oi = __shfl_down_sync(0xffffffffu, bi, off);
                if (ov > bv || (ov == bv && oi < bi)) { bv = ov; bi = oi; }
            }
            bi = __shfl_sync(0xffffffffu, bi, 0);
            if (tid == 0) {
                g_ctx[(b * T + t) * KNN + k] = sh_colsum[bi] / (float)CH;
                sh_pd[bi] = -INFINITY;
            }
            __syncwarp();
        }
        if (tid == 0) {
            __threadfence();
            atomicAdd(&g_done, 1u);
        }
    }
}

// ---------------- inner align (r<12): branchless 6+1-slot window, STG.128 ----------------
__device__ void inner_body(const float* __restrict__ x, float* __restrict__ out, int blk) {
    int cblk = blk % CSPLIT_IN;  blk /= CSPLIT_IN;
    int tile = blk % NT_TILES;   blk /= NT_TILES;
    int r    = blk % RES_INNER;
    int b    = blk / RES_INNER;
    const int tid = threadIdx.x;

    const int tsz = (tile < 4) ? 1024 : (DT - 4096);   // 904 on last tile (mult of 4)
    const int idx = tid * 4;
    if (idx >= tsz) return;

    const int dt0 = tile * 1024 + idx;                 // 4 consecutive dt, same d row
    const int d   = dt0 / T;
    const int t0  = dt0 - d * T;
    const float cl = (float)(d + 1);

    int   fl[4];
    float wlo[4], whi[4];
    bool  va[4];

    #pragma unroll
    for (int j = 0; j < 4; ++j) {
        int t = t0 + j;
        va[j] = (t + d) < T;
        float start = va[j] ? ((float)t - cl * 0.5f) : 0.0f;
        float end   = va[j] ? ((float)(t + d) + cl * 0.5f) : 0.0f;
        float binw  = __fdiv_rn(end - start, (float)RES_INNER);
        float coord = __fadd_rn(start, __fmul_rn((float)r + 0.5f, binw));
        bool valid  = (coord >= -1.0f) && (coord <= (float)T);
        float lof   = floorf(coord);
        float frac  = coord - lof;
        fl[j]  = (int)lof;
        wlo[j] = valid ? (1.0f - frac) : 0.0f;
        whi[j] = valid ? frac : 0.0f;
    }

    // window base + clamped load indices
    const int B = fl[0];
    int q[6];
    #pragma unroll
    for (int i = 0; i < 6; ++i) {
        int p = B + i;
        q[i] = p < 0 ? 0 : (p > T - 1 ? T - 1 : p);
    }

    // 4x7 weight matrix: slots 0..5 = window, slot 6 = x[0] (anchor-invalid rows)
    float W[4][7];
    bool need6 = false;
    #pragma unroll
    for (int j = 0; j < 4; ++j) {
        int ol = fl[j] - B; ol = ol < 0 ? 0 : (ol > 5 ? 5 : ol);
        int oh = (fl[j] == -1) ? (ol + 2) : (ol + 1); oh = oh > 5 ? 5 : oh;
        float a = va[j] ? wlo[j] : 0.0f;
        float h = va[j] ? whi[j] : 0.0f;
        #pragma unroll
        for (int i = 0; i < 6; ++i)
            W[j][i] = (ol == i ? a : 0.0f) + (oh == i ? h : 0.0f);
        W[j][6] = va[j] ? 0.0f : 1.0f;
        need6 |= !va[j];
    }

    const int c0 = cblk * CPB_IN;
    const float* src = x + ((size_t)b * CH + c0) * T;
    float* gdst = out + ((b * CH + c0) * RES_TOT + r) * DT + dt0;

    #pragma unroll
    for (int c = 0; c < CPB_IN; ++c) {
        float v0 = __ldg(src + q[0]);
        float v1 = __ldg(src + q[1]);
        float v2 = __ldg(src + q[2]);
        float v3 = __ldg(src + q[3]);
        float v4 = __ldg(src + q[4]);
        float v5 = __ldg(src + q[5]);
        float v6 = need6 ? __ldg(src) : 0.0f;
        float4 o;
        #pragma unroll
        for (int j = 0; j < 4; ++j) {
            float acc = W[j][0] * v0;
            acc = fmaf(W[j][1], v1, acc);
            acc = fmaf(W[j][2], v2, acc);
            acc = fmaf(W[j][3], v3, acc);
            acc = fmaf(W[j][4], v4, acc);
            acc = fmaf(W[j][5], v5, acc);
            acc = fmaf(W[j][6], v6, acc);
            (&o.x)[j] = acc;
        }
        *reinterpret_cast<float4*>(gdst) = o;
        src  += T;
        gdst += OUT_C_STRIDE;
    }
}

// ---------------- ctx align (r>=12): 3-coeff precompute, direct STG.128 ----------------
__device__ void ctx_body(float* __restrict__ out, int blk) {
    int cblk = blk % CSPLIT_CTX;  blk /= CSPLIT_CTX;
    int tile = blk % NT_TILES;    blk /= NT_TILES;
    int rr   = blk % RES_CTX;
    int b    = blk / RES_CTX;
    const int tid = threadIdx.x;

    // wait for kNN blocks (IDs 0..199 guaranteed wave-1 resident)
    if (tid == 0) {
        while (atomicAdd(&g_done, 0u) < (unsigned)KNN_GRID) { __nanosleep(64); }
        __threadfence();
    }
    __syncthreads();

    const int tsz = (tile < 4) ? 1024 : (DT - 4096);
    const int idx = tid * 4;

    if (idx < tsz) {
        const int dt0 = tile * 1024 + idx;
        const int d   = dt0 / T;
        const int t0  = dt0 - d * T;

        float a0[4], a1[4], a2[4];
        #pragma unroll
        for (int j = 0; j < 4; ++j) {
            int t = t0 + j;
            bool va     = (t + d) < T;
            float cl    = (float)(d + 1);
            float start = va ? ((float)t - cl * 0.5f) : 0.0f;
            float end   = va ? ((float)(t + d) + cl * 0.5f) : 0.0f;
            float binw  = (end - start) * 0.0625f;       // /16 exact
            float coord = __fadd_rn(start, __fmul_rn((float)rr + 0.5f, binw));
            bool valid  = (coord >= -1.0f) && (coord <= (float)KNN);
            float lof   = floorf(coord);
            float frac  = coord - lof;
            int loi = (int)lof;
            loi = loi < 0 ? 0 : (loi > KNN - 1 ? KNN - 1 : loi);
            int hii = loi + 1 > KNN - 1 ? KNN - 1 : loi + 1;
            float wlo = valid ? (1.0f - frac) : 0.0f;
            float whi = valid ? frac : 0.0f;
            float c0a = 0.f, c1a = 0.f, c2a = 0.f;
            if (loi == 0) c0a += wlo; else if (loi == 1) c1a += wlo; else c2a += wlo;
            if (hii == 0) c0a += whi; else if (hii == 1) c1a += whi; else c2a += whi;
            a0[j] = c0a; a1[j] = c1a; a2[j] = c2a;
        }

        const int c0 = cblk * CPB_CTX;
        const float* cr = g_ctx + (b * CH + c0) * KNN;
        float* gdst = out + ((b * CH + c0) * RES_TOT + (RES_INNER + rr)) * DT + dt0;

        #pragma unroll 4
        for (int c = 0; c < CPB_CTX; ++c) {
            float g0 = __ldg(cr + 0), g1 = __ldg(cr + 1), g2 = __ldg(cr + 2);
            float4 o;
            o.x = fmaf(a2[0], g2, fmaf(a1[0], g1, a0[0] * g0));
            o.y = fmaf(a2[1], g2, fmaf(a1[1], g1, a0[1] * g0));
            o.z = fmaf(a2[2], g2, fmaf(a1[2], g1, a0[2] * g0));
            o.w = fmaf(a2[3], g2, fmaf(a1[3], g1, a0[3] * g0));
            *reinterpret_cast<float4*>(gdst) = o;
            cr   += KNN;
            gdst += OUT_C_STRIDE;
        }
    }

    // last ctx block resets counters for deterministic graph replay
    __syncthreads();
    if (tid == 0) {
        unsigned v = atomicAdd(&g_exit, 1u);
        if (v == (unsigned)(CTX_GRID - 1)) {
            g_done = 0;
            g_exit = 0;
            __threadfence();
        }
    }
}

// ---------------- fused kernel ----------------
__global__ void __launch_bounds__(256)
graph_align_fused(const float* __restrict__ x, float* __restrict__ out) {
    unsigned bid = blockIdx.x;
    if (bid < KNN_GRID) {
        knn_body(x, (int)bid);
    } else if (bid < KNN_GRID + INNER_GRID) {
        inner_body(x, out, (int)(bid - KNN_GRID));
    } else {
        ctx_body(out, (int)(bid - KNN_GRID - INNER_GRID));
    }
}

extern "C" void kernel_launch(void* const* d_in, const int* in_sizes, int n_in,
                              void* d_out, int out_size) {
    const float* x = (const float*)d_in[0];
    float* out = (float*)d_out;
    graph_align_fused<<<TOTAL_GRID, 256>>>(x, out);
}